// round 5
// baseline (speedup 1.0000x reference)
#include <cuda_runtime.h>
#include <stdint.h>

// out[i,j] = 2*x[i,j] + 5 - (i+j), x: [8192, 8192] fp32.
// Persistent grid-stride HBM-streaming kernel: exactly one wave of CTAs
// (148 SMs x 8 CTAs) loops over 16K chunks -> zero wave transitions, no
// tail-wave quantization. Per iteration: 4x front-batched float4 loads
// (MLP=4, measured optimum), cache-streaming load/store hints.

#define N_DIM 8192
#define M_DIM 8192
#define VEC_PER_ROW_LOG2 11             // 8192/4 = 2048 float4 per row
#define VEC_PER_ROW (1 << VEC_PER_ROW_LOG2)
#define UNROLL 4
#define THREADS 256
#define CHUNK_VEC (THREADS * UNROLL)    // 1024 float4 per chunk
#define NUM_CHUNKS ((N_DIM * M_DIM / 4) / CHUNK_VEC)  // 16384
#define GRID_BLOCKS (148 * 8)           // one full wave at occ 8

__global__ __launch_bounds__(THREADS) void fused_affine_outer_kernel(
    const float4* __restrict__ x, float4* __restrict__ out)
{
    for (unsigned int c = blockIdx.x; c < NUM_CHUNKS; c += GRID_BLOCKS) {
        unsigned int base = c * CHUNK_VEC + threadIdx.x;

        float4 in[UNROLL];
#pragma unroll
        for (int k = 0; k < UNROLL; k++) {
            in[k] = __ldcs(&x[base + k * THREADS]);
        }

#pragma unroll
        for (int k = 0; k < UNROLL; k++) {
            unsigned int v  = base + k * THREADS;
            unsigned int i  = v >> VEC_PER_ROW_LOG2;          // row
            unsigned int j4 = (v & (VEC_PER_ROW - 1)) << 2;   // col of lane 0
            float b = 5.0f - (float)(i + j4);

            float4 o;
            o.x = fmaf(in[k].x, 2.0f, b);
            o.y = fmaf(in[k].y, 2.0f, b - 1.0f);
            o.z = fmaf(in[k].z, 2.0f, b - 2.0f);
            o.w = fmaf(in[k].w, 2.0f, b - 3.0f);
            __stcs(&out[v], o);
        }
    }
}

extern "C" void kernel_launch(void* const* d_in, const int* in_sizes, int n_in,
                              void* d_out, int out_size)
{
    const float4* x = (const float4*)d_in[0];
    float4* out = (float4*)d_out;

    fused_affine_outer_kernel<<<GRID_BLOCKS, THREADS>>>(x, out);
}

// round 6
// speedup vs baseline: 1.1362x; 1.1362x over previous
#include <cuda_runtime.h>
#include <stdint.h>

// out[i,j] = 2*x[i,j] + 5 - (i+j), x: [8192, 8192] fp32.
// Flat-grid HBM-streaming kernel (persistent variant measured WORSE: per-CTA
// loop serializes loads behind prior stores; flat grid lets GigaThread keep
// fresh front-batched loads in flight). 4x float4 loads per thread (MLP=4,
// measured optimum), 512-thread blocks for 32KB contiguous per-CTA extents,
// cache-streaming (evict-first) hints since there is zero reuse.

#define N_DIM 8192
#define M_DIM 8192
#define VEC_PER_ROW_LOG2 11             // 8192/4 = 2048 float4 per row
#define VEC_PER_ROW (1 << VEC_PER_ROW_LOG2)
#define UNROLL 4
#define THREADS 512

__global__ __launch_bounds__(THREADS) void fused_affine_outer_kernel(
    const float4* __restrict__ x, float4* __restrict__ out)
{
    // Each block owns a contiguous chunk of UNROLL*THREADS vectors;
    // within each unroll step the warp's accesses are fully coalesced.
    unsigned int base = blockIdx.x * (THREADS * UNROLL) + threadIdx.x;

    float4 in[UNROLL];
#pragma unroll
    for (int k = 0; k < UNROLL; k++) {
        in[k] = __ldcs(&x[base + k * THREADS]);
    }

#pragma unroll
    for (int k = 0; k < UNROLL; k++) {
        unsigned int v  = base + k * THREADS;
        unsigned int i  = v >> VEC_PER_ROW_LOG2;          // row
        unsigned int j4 = (v & (VEC_PER_ROW - 1)) << 2;   // col of lane 0
        float b = 5.0f - (float)(i + j4);

        float4 o;
        o.x = fmaf(in[k].x, 2.0f, b);
        o.y = fmaf(in[k].y, 2.0f, b - 1.0f);
        o.z = fmaf(in[k].z, 2.0f, b - 2.0f);
        o.w = fmaf(in[k].w, 2.0f, b - 3.0f);
        __stcs(&out[v], o);
    }
}

extern "C" void kernel_launch(void* const* d_in, const int* in_sizes, int n_in,
                              void* d_out, int out_size)
{
    const float4* x = (const float4*)d_in[0];
    float4* out = (float4*)d_out;

    const unsigned int total_vec = (N_DIM * M_DIM) / 4;         // 16,777,216
    const unsigned int blocks = total_vec / (THREADS * UNROLL); // 8,192

    fused_affine_outer_kernel<<<blocks, THREADS>>>(x, out);
}